// round 6
// baseline (speedup 1.0000x reference)
#include <cuda_runtime.h>
#include <cstdint>

#define BB 16
#define NN 25200
#define NCC 80
#define ROWW 85
#define MAXDET 300
#define NPRE 1024
#define GCAP 8192
#define NBINS 1536
#define BASE_BITS 0x3EC00000u
#define HSHIFT 13
#define RPB 64
#define GRID_X ((NN + RPB - 1) / RPB)
#define CAPC 128
#define RESCUE_BLKS 32

typedef unsigned long long u64;
typedef unsigned int u32;
typedef unsigned short u16;

// ---------------- scratch ----------------
static __device__ u32 g_hist[BB * NBINS];
static __device__ int g_beta[BB];
static __device__ u32 g_flag[BB];
static __device__ u32 g_preCnt[BB];
static __device__ u64 g_preRaw[BB * GCAP];
static __device__ u64 g_preSorted[BB * NPRE];
static __device__ u32 g_preN[BB];
static __device__ unsigned char g_keep[BB * NPRE];

__device__ __forceinline__ int score_bin(u32 bits) {
    int bin = (int)((bits - BASE_BITS) >> HSHIFT);
    return bin > (NBINS - 1) ? (NBINS - 1) : bin;
}
#define PB90 (score_bin(0x3F666666u))   /* bin of 0.90f */
#define PB96 (score_bin(0x3F75C28Fu))   /* bin of 0.96f */

__device__ __forceinline__ void warp_store(int b, bool pass, u64 key) {
    u32 m = __ballot_sync(0xffffffffu, pass);
    if (!m) return;
    int lane = threadIdx.x & 31;
    int leader = __ffs(m) - 1;
    u32 base = 0;
    if (lane == leader) base = atomicAdd(&g_preCnt[b], (u32)__popc(m));
    base = __shfl_sync(0xffffffffu, base, leader);
    if (pass) {
        u32 slot = base + __popc(m & ((1u << lane) - 1u));
        if (slot < GCAP) g_preRaw[(size_t)b * GCAP + slot] = key;
    }
}

// ---------------- kernels ----------------
__global__ void k_init() {
    int i = blockIdx.x * blockDim.x + threadIdx.x;
    int st = gridDim.x * blockDim.x;
    for (int k = i; k < BB * NBINS; k += st) g_hist[k] = 0;
    for (int k = i; k < BB * NPRE / 4; k += st) ((u32*)g_keep)[k] = 0;
    if (i < BB) { g_preCnt[i] = 0; g_flag[i] = 0; }
}

// single fused streaming pass: staged coalesced load of 64 rows,
// histogram scores > 0.9, store candidates with bin > PB96
__global__ void __launch_bounds__(256) k_pass1(const float* __restrict__ pred) {
    __shared__ float srow[RPB * ROWW];   // 21760 B
    __shared__ u32 sh[NBINS];            // 6144 B
    int b = blockIdx.y, tid = threadIdx.x;
    int row0 = blockIdx.x * RPB;
    int nrows = min(RPB, NN - row0);
    for (int i = tid; i < NBINS; i += 256) sh[i] = 0;
    const float4* src = (const float4*)(pred + ((size_t)b * NN + row0) * ROWW);
    int nv = nrows * ROWW / 4;
    for (int i = tid; i < nv; i += 256) ((float4*)srow)[i] = src[i];
    __syncthreads();

    int warp = tid >> 5, lane = tid & 31;
    for (int r = warp; r < nrows; r += 8) {
        float obj = srow[r * ROWW + 4];
        if (obj <= 0.4f) continue;
        int rowg = row0 + r;
#pragma unroll
        for (int k = 0; k < 3; k++) {
            int c = k * 32 + lane;
            bool pass = false;
            u64 key = 0;
            if (c < NCC) {
                float s = __fmul_rn(srow[r * ROWW + 5 + c], obj);
                if (s > 0.9f) {
                    u32 bits = __float_as_uint(s);
                    int bin = score_bin(bits);
                    atomicAdd(&sh[bin], 1u);
                    if (bin > PB96) {
                        pass = true;
                        u32 flat = (u32)rowg * NCC + (u32)c;
                        key = ((u64)bits << 21) | (u64)(0x1FFFFFu - flat);
                    }
                }
            }
            warp_store(b, pass, key);
        }
    }
    __syncthreads();
    for (int i = tid; i < NBINS; i += 256)
        if (sh[i]) atomicAdd(&g_hist[b * NBINS + i], sh[i]);
}

// exact top-NPRE boundary bin from the (partial, >PB90-complete) histogram
__global__ void k_select() {
    __shared__ u32 h[NBINS];
    __shared__ u32 part[256];
    int b = blockIdx.x, tid = threadIdx.x;
    for (int i = tid; i < NBINS; i += 256)
        h[i] = (i > PB90) ? g_hist[b * NBINS + i] : 0u;
    __syncthreads();
    u32 ps = 0;
    for (int k = 0; k < 6; k++) ps += h[tid * 6 + k];
    part[tid] = ps;
    __syncthreads();
    if (tid == 0) {
        u32 cum = 0; int beta = -1;
        for (int t = 255; t >= 0; --t) {
            if (cum + part[t] >= (u32)NPRE) {
                for (int bin = t * 6 + 5; bin >= t * 6; --bin) {
                    u32 c = h[bin];
                    if (cum + c >= (u32)NPRE) { beta = bin; break; }
                    cum += c;
                }
                break;
            }
            cum += part[t];
        }
        if (beta < 0 || beta <= PB96) g_flag[b] = 1;   // rescue
        else g_beta[b] = beta;
    }
}

// ---- rescue path: grid-stride so the no-op case is ~free ----
__global__ void __launch_bounds__(256) k_hist_lo(const float* __restrict__ pred) {
    int b = blockIdx.y;
    if (!g_flag[b]) return;
    __shared__ u32 sh[NBINS];
    int tid = threadIdx.x;
    for (int i = tid; i < NBINS; i += 256) sh[i] = 0;
    __syncthreads();
    int warp = tid >> 5, lane = tid & 31;
    for (int row = blockIdx.x * 8 + warp; row < NN; row += RESCUE_BLKS * 8) {
        const float* q = pred + ((size_t)b * NN + row) * ROWW;
        float obj = q[4];
        if (obj > 0.4f) {
#pragma unroll
            for (int k = 0; k < 3; k++) {
                int c = k * 32 + lane;
                if (c < NCC) {
                    float s = __fmul_rn(q[5 + c], obj);
                    if (s > 0.4f && !(s > 0.9f))
                        atomicAdd(&sh[score_bin(__float_as_uint(s))], 1u);
                }
            }
        }
    }
    __syncthreads();
    for (int i = tid; i < NBINS; i += 256)
        if (sh[i]) atomicAdd(&g_hist[b * NBINS + i], sh[i]);
}

__global__ void k_select2() {
    __shared__ u32 h[NBINS];
    __shared__ u32 part[256];
    int b = blockIdx.x, tid = threadIdx.x;
    if (!g_flag[b]) return;
    for (int i = tid; i < NBINS; i += 256) h[i] = g_hist[b * NBINS + i];
    __syncthreads();
    u32 ps = 0;
    for (int k = 0; k < 6; k++) ps += h[tid * 6 + k];
    part[tid] = ps;
    __syncthreads();
    if (tid == 0) {
        u32 cum = 0; int beta = 0;
        for (int t = 255; t >= 0; --t) {
            if (cum + part[t] >= (u32)NPRE) {
                for (int bin = t * 6 + 5; bin >= t * 6; --bin) {
                    u32 c = h[bin];
                    if (cum + c >= (u32)NPRE) { beta = bin; break; }
                    cum += c;
                }
                break;
            }
            cum += part[t];
        }
        g_beta[b] = beta;
        g_preCnt[b] = 0;
    }
}

__global__ void __launch_bounds__(256) k_regather(const float* __restrict__ pred) {
    int b = blockIdx.y;
    if (!g_flag[b]) return;
    int beta = g_beta[b];
    int tid = threadIdx.x;
    int warp = tid >> 5, lane = tid & 31;
    for (int row = blockIdx.x * 8 + warp; row < NN; row += RESCUE_BLKS * 8) {
        const float* q = pred + ((size_t)b * NN + row) * ROWW;
        float obj = q[4];
        bool rowok = (obj > 0.4f);
#pragma unroll
        for (int k = 0; k < 3; k++) {
            int c = k * 32 + lane;
            bool pass = false;
            u64 key = 0;
            if (rowok && c < NCC) {
                float s = __fmul_rn(q[5 + c], obj);
                if (s > 0.4f) {
                    u32 bits = __float_as_uint(s);
                    if (score_bin(bits) >= beta) {
                        pass = true;
                        u32 flat = (u32)row * NCC + (u32)c;
                        key = ((u64)bits << 21) | (u64)(0x1FFFFFu - flat);
                    }
                }
            }
            warp_store(b, pass, key);
        }
    }
}

// one block per batch: filter raw by bin>=beta, bitonic sort desc, keep NPRE
__global__ void __launch_bounds__(1024) k_sort() {
    extern __shared__ u64 sk[];
    __shared__ u32 scount;
    int b = blockIdx.x, tid = threadIdx.x;
    if (tid == 0) scount = 0;
    __syncthreads();
    int beta = g_beta[b];
    u32 cnt = min(g_preCnt[b], (u32)GCAP);
    for (u32 i = tid; i < cnt; i += 1024) {
        u64 key = g_preRaw[(size_t)b * GCAP + i];
        if (score_bin((u32)(key >> 21)) >= beta) {
            u32 p = atomicAdd(&scount, 1u);
            sk[p] = key;
        }
    }
    __syncthreads();
    u32 fc = min(scount, (u32)GCAP);
    u32 P = 2;
    while (P < fc) P <<= 1;
    for (u32 i = fc + tid; i < P; i += 1024) sk[i] = 0ull;
    __syncthreads();
    for (u32 k = 2; k <= P; k <<= 1) {
        for (u32 j = k >> 1; j; j >>= 1) {
            for (u32 i = tid; i < P; i += 1024) {
                u32 l = i ^ j;
                if (l > i) {
                    u64 a = sk[i], c = sk[l];
                    bool desc = ((i & k) == 0);
                    if ((a < c) == desc) { sk[i] = c; sk[l] = a; }
                }
            }
            __syncthreads();
        }
    }
    if (tid == 0) g_preN[b] = min(fc, (u32)NPRE);
    for (int i = tid; i < NPRE; i += 1024)
        g_preSorted[(size_t)b * NPRE + i] = (i < (int)P) ? sk[i] : 0ull;
}

// warp per (class,batch): greedy NMS on sorted prefix, reference-exact FP
__global__ void __launch_bounds__(256) k_nms(const float* __restrict__ pred) {
    __shared__ u16 spos[8][CAPC];
    __shared__ float4 sbox[8][CAPC];
    __shared__ float sarea[8][CAPC];
    __shared__ unsigned char ssup[8][CAPC];
    int b = blockIdx.y, tid = threadIdx.x;
    int w = tid >> 5, lane = tid & 31;
    int myc = blockIdx.x * 8 + w;
    u32 N = g_preN[b];
    const u64* ps = &g_preSorted[(size_t)b * NPRE];
    u32 base = 0;
    for (u32 i = lane; i < ((N + 31) & ~31u); i += 32) {
        bool match = false;
        if (i < N) {
            u32 flat = 0x1FFFFFu - (u32)(ps[i] & 0x1FFFFFu);
            match = (flat % NCC) == (u32)myc;
        }
        u32 m = __ballot_sync(0xffffffffu, match);
        if (match) {
            u32 idx = base + __popc(m & ((1u << lane) - 1u));
            if (idx < CAPC) spos[w][idx] = (u16)i;
        }
        base += __popc(m);
    }
    u32 cnt = min(base, (u32)CAPC);
    float coff = (float)myc * 4096.0f;
    for (u32 j = lane; j < cnt; j += 32) {
        u32 i = spos[w][j];
        u32 flat = 0x1FFFFFu - (u32)(ps[i] & 0x1FFFFFu);
        u32 n = flat / NCC;
        const float* q = pred + ((size_t)b * NN + n) * ROWW;
        float cx = q[0], cy = q[1], ww = q[2], hh = q[3];
        float x1 = __fsub_rn(cx, __fmul_rn(0.5f, ww));
        float y1 = __fsub_rn(cy, __fmul_rn(0.5f, hh));
        float x2 = __fadd_rn(cx, __fmul_rn(0.5f, ww));
        float y2 = __fadd_rn(cy, __fmul_rn(0.5f, hh));
        float ox1 = __fadd_rn(x1, coff), oy1 = __fadd_rn(y1, coff);
        float ox2 = __fadd_rn(x2, coff), oy2 = __fadd_rn(y2, coff);
        sbox[w][j] = make_float4(ox1, oy1, ox2, oy2);
        sarea[w][j] = __fmul_rn(__fsub_rn(ox2, ox1), __fsub_rn(oy2, oy1));
        ssup[w][j] = 0;
    }
    __syncwarp();
    for (u32 m = 0; m < cnt; m++) {
        if (ssup[w][m]) continue;
        if (lane == 0) g_keep[(size_t)b * NPRE + spos[w][m]] = 1;
        float4 bm = sbox[w][m];
        float am = sarea[w][m];
        for (u32 j = m + 1 + lane; j < cnt; j += 32) {
            if (ssup[w][j]) continue;
            float4 bj = sbox[w][j];
            float ltx = fmaxf(bm.x, bj.x), lty = fmaxf(bm.y, bj.y);
            float rbx = fminf(bm.z, bj.z), rby = fminf(bm.w, bj.w);
            float wx = fmaxf(__fsub_rn(rbx, ltx), 0.0f);
            float wy = fmaxf(__fsub_rn(rby, lty), 0.0f);
            float inter = __fmul_rn(wx, wy);
            if (inter > 0.0f) {
                float den = __fadd_rn(__fsub_rn(__fadd_rn(am, sarea[w][j]), inter), 1e-9f);
                if (__fdiv_rn(inter, den) > 0.5f) ssup[w][j] = 1;
            }
        }
        __syncwarp();
    }
}

// block per batch: prefix-scan keep flags, emit first 300 in prefix order
__global__ void __launch_bounds__(256) k_final(const float* __restrict__ pred,
                                               float* __restrict__ out) {
    __shared__ u32 part[256];
    int b = blockIdx.x, tid = threadIdx.x;
    u32 N = g_preN[b];
    float* ob = out + (size_t)b * MAXDET * 6;
    for (int k = tid; k < MAXDET * 6; k += 256) ob[k] = 0.0f;
    u32 s = 0;
    unsigned char f[4];
#pragma unroll
    for (int t = 0; t < 4; t++) {
        u32 i = tid * 4 + t;
        f[t] = (i < N) ? g_keep[(size_t)b * NPRE + i] : 0;
        s += f[t];
    }
    part[tid] = s;
    __syncthreads();
    for (int off = 1; off < 256; off <<= 1) {
        u32 v = (tid >= off) ? part[tid - off] : 0;
        __syncthreads();
        part[tid] += v;
        __syncthreads();
    }
    u32 r = part[tid] - s;
#pragma unroll
    for (int t = 0; t < 4; t++) {
        u32 i = tid * 4 + t;
        if (f[t]) {
            if (r < (u32)MAXDET) {
                u64 key = g_preSorted[(size_t)b * NPRE + i];
                u32 flat = 0x1FFFFFu - (u32)(key & 0x1FFFFFu);
                u32 n = flat / NCC, c = flat - n * NCC;
                const float* q = pred + ((size_t)b * NN + n) * ROWW;
                float cx = q[0], cy = q[1], ww = q[2], hh = q[3];
                float* o = ob + r * 6;
                o[0] = __fsub_rn(cx, __fmul_rn(0.5f, ww));
                o[1] = __fsub_rn(cy, __fmul_rn(0.5f, hh));
                o[2] = __fadd_rn(cx, __fmul_rn(0.5f, ww));
                o[3] = __fadd_rn(cy, __fmul_rn(0.5f, hh));
                o[4] = __uint_as_float((u32)(key >> 21));
                o[5] = (float)c;
            }
            r++;
        }
    }
}

extern "C" void kernel_launch(void* const* d_in, const int* in_sizes, int n_in,
                              void* d_out, int out_size) {
    const float* pred = (const float*)d_in[0];
    float* out = (float*)d_out;
    (void)in_sizes; (void)n_in; (void)out_size;

    cudaFuncSetAttribute(k_sort, cudaFuncAttributeMaxDynamicSharedMemorySize, GCAP * 8);

    k_init<<<64, 256>>>();
    k_pass1<<<dim3(GRID_X, BB), 256>>>(pred);
    k_select<<<BB, 256>>>();
    k_hist_lo<<<dim3(RESCUE_BLKS, BB), 256>>>(pred);     // rescue (grid-stride, ~free)
    k_select2<<<BB, 256>>>();                             // rescue
    k_regather<<<dim3(RESCUE_BLKS, BB), 256>>>(pred);     // rescue (grid-stride, ~free)
    k_sort<<<BB, 1024, GCAP * 8>>>();
    k_nms<<<dim3(NCC / 8, BB), 256>>>(pred);
    k_final<<<BB, 256>>>(pred, out);
}

// round 7
// speedup vs baseline: 1.0078x; 1.0078x over previous
#include <cuda_runtime.h>
#include <cstdint>

#define BB 16
#define NN 25200
#define NCC 80
#define ROWW 85
#define MAXDET 300
#define NPRE 1024
#define GCAP 8192
#define NBINS 1536
#define BASE_BITS 0x3EC00000u
#define HSHIFT 13
#define RPB 64
#define GRID_X ((NN + RPB - 1) / RPB)
#define CAPC 128
#define RESCUE_BLKS 32

typedef unsigned long long u64;
typedef unsigned int u32;
typedef unsigned short u16;

// ---------------- scratch ----------------
static __device__ u32 g_hist[BB * NBINS];
static __device__ int g_beta[BB];
static __device__ u32 g_flag[BB];
static __device__ u32 g_preCnt[BB];
static __device__ u64 g_preRaw[BB * GCAP];
static __device__ u64 g_preSorted[BB * NPRE];
static __device__ u32 g_preN[BB];
static __device__ unsigned char g_keep[BB * NPRE];

__device__ __forceinline__ int score_bin(u32 bits) {
    int bin = (int)((bits - BASE_BITS) >> HSHIFT);
    return bin > (NBINS - 1) ? (NBINS - 1) : bin;
}
#define PB90 (score_bin(0x3F666666u))   /* bin of 0.90f */
#define PB96 (score_bin(0x3F75C28Fu))   /* bin of 0.96f */

__device__ __forceinline__ void warp_store(int b, bool pass, u64 key) {
    u32 m = __ballot_sync(0xffffffffu, pass);
    if (!m) return;
    int lane = threadIdx.x & 31;
    int leader = __ffs(m) - 1;
    u32 base = 0;
    if (lane == leader) base = atomicAdd(&g_preCnt[b], (u32)__popc(m));
    base = __shfl_sync(0xffffffffu, base, leader);
    if (pass) {
        u32 slot = base + __popc(m & ((1u << lane) - 1u));
        if (slot < GCAP) g_preRaw[(size_t)b * GCAP + slot] = key;
    }
}

// ---------------- kernels ----------------
__global__ void k_init() {
    int i = blockIdx.x * blockDim.x + threadIdx.x;
    int st = gridDim.x * blockDim.x;
    for (int k = i; k < BB * NBINS; k += st) g_hist[k] = 0;
    for (int k = i; k < BB * NPRE / 4; k += st) ((u32*)g_keep)[k] = 0;
    if (i < BB) { g_preCnt[i] = 0; g_flag[i] = 0; }
}

// single fused streaming pass: staged coalesced load of 64 rows,
// histogram scores > 0.9, store candidates with bin > PB96
__global__ void __launch_bounds__(256) k_pass1(const float* __restrict__ pred) {
    __shared__ float srow[RPB * ROWW];   // 21760 B
    __shared__ u32 sh[NBINS];            // 6144 B
    int b = blockIdx.y, tid = threadIdx.x;
    int row0 = blockIdx.x * RPB;
    int nrows = min(RPB, NN - row0);
    for (int i = tid; i < NBINS; i += 256) sh[i] = 0;
    const float4* src = (const float4*)(pred + ((size_t)b * NN + row0) * ROWW);
    int nv = nrows * ROWW / 4;
    for (int i = tid; i < nv; i += 256) ((float4*)srow)[i] = src[i];
    __syncthreads();

    int warp = tid >> 5, lane = tid & 31;
    for (int r = warp; r < nrows; r += 8) {
        float obj = srow[r * ROWW + 4];
        if (obj <= 0.4f) continue;
        int rowg = row0 + r;
#pragma unroll
        for (int k = 0; k < 3; k++) {
            int c = k * 32 + lane;
            bool pass = false;
            u64 key = 0;
            if (c < NCC) {
                float s = __fmul_rn(srow[r * ROWW + 5 + c], obj);
                if (s > 0.9f) {
                    u32 bits = __float_as_uint(s);
                    int bin = score_bin(bits);
                    atomicAdd(&sh[bin], 1u);
                    if (bin > PB96) {
                        pass = true;
                        u32 flat = (u32)rowg * NCC + (u32)c;
                        key = ((u64)bits << 21) | (u64)(0x1FFFFFu - flat);
                    }
                }
            }
            warp_store(b, pass, key);
        }
    }
    __syncthreads();
    for (int i = tid; i < NBINS; i += 256)
        if (sh[i]) atomicAdd(&g_hist[b * NBINS + i], sh[i]);
}

// exact top-NPRE boundary bin from the (partial, >PB90-complete) histogram
__global__ void k_select() {
    __shared__ u32 h[NBINS];
    __shared__ u32 part[256];
    int b = blockIdx.x, tid = threadIdx.x;
    for (int i = tid; i < NBINS; i += 256)
        h[i] = (i > PB90) ? g_hist[b * NBINS + i] : 0u;
    __syncthreads();
    u32 ps = 0;
    for (int k = 0; k < 6; k++) ps += h[tid * 6 + k];
    part[tid] = ps;
    __syncthreads();
    if (tid == 0) {
        u32 cum = 0; int beta = -1;
        for (int t = 255; t >= 0; --t) {
            if (cum + part[t] >= (u32)NPRE) {
                for (int bin = t * 6 + 5; bin >= t * 6; --bin) {
                    u32 c = h[bin];
                    if (cum + c >= (u32)NPRE) { beta = bin; break; }
                    cum += c;
                }
                break;
            }
            cum += part[t];
        }
        if (beta < 0 || beta <= PB96) g_flag[b] = 1;   // rescue
        else g_beta[b] = beta;
    }
}

// ---- rescue path: grid-stride so the no-op case is ~free ----
__global__ void __launch_bounds__(256) k_hist_lo(const float* __restrict__ pred) {
    int b = blockIdx.y;
    if (!g_flag[b]) return;
    __shared__ u32 sh[NBINS];
    int tid = threadIdx.x;
    for (int i = tid; i < NBINS; i += 256) sh[i] = 0;
    __syncthreads();
    int warp = tid >> 5, lane = tid & 31;
    for (int row = blockIdx.x * 8 + warp; row < NN; row += RESCUE_BLKS * 8) {
        const float* q = pred + ((size_t)b * NN + row) * ROWW;
        float obj = q[4];
        if (obj > 0.4f) {
#pragma unroll
            for (int k = 0; k < 3; k++) {
                int c = k * 32 + lane;
                if (c < NCC) {
                    float s = __fmul_rn(q[5 + c], obj);
                    if (s > 0.4f && !(s > 0.9f))
                        atomicAdd(&sh[score_bin(__float_as_uint(s))], 1u);
                }
            }
        }
    }
    __syncthreads();
    for (int i = tid; i < NBINS; i += 256)
        if (sh[i]) atomicAdd(&g_hist[b * NBINS + i], sh[i]);
}

__global__ void k_select2() {
    __shared__ u32 h[NBINS];
    __shared__ u32 part[256];
    int b = blockIdx.x, tid = threadIdx.x;
    if (!g_flag[b]) return;
    for (int i = tid; i < NBINS; i += 256) h[i] = g_hist[b * NBINS + i];
    __syncthreads();
    u32 ps = 0;
    for (int k = 0; k < 6; k++) ps += h[tid * 6 + k];
    part[tid] = ps;
    __syncthreads();
    if (tid == 0) {
        u32 cum = 0; int beta = 0;
        for (int t = 255; t >= 0; --t) {
            if (cum + part[t] >= (u32)NPRE) {
                for (int bin = t * 6 + 5; bin >= t * 6; --bin) {
                    u32 c = h[bin];
                    if (cum + c >= (u32)NPRE) { beta = bin; break; }
                    cum += c;
                }
                break;
            }
            cum += part[t];
        }
        g_beta[b] = beta;
        g_preCnt[b] = 0;
    }
}

__global__ void __launch_bounds__(256) k_regather(const float* __restrict__ pred) {
    int b = blockIdx.y;
    if (!g_flag[b]) return;
    int beta = g_beta[b];
    int tid = threadIdx.x;
    int warp = tid >> 5, lane = tid & 31;
    for (int row = blockIdx.x * 8 + warp; row < NN; row += RESCUE_BLKS * 8) {
        const float* q = pred + ((size_t)b * NN + row) * ROWW;
        float obj = q[4];
        bool rowok = (obj > 0.4f);
#pragma unroll
        for (int k = 0; k < 3; k++) {
            int c = k * 32 + lane;
            bool pass = false;
            u64 key = 0;
            if (rowok && c < NCC) {
                float s = __fmul_rn(q[5 + c], obj);
                if (s > 0.4f) {
                    u32 bits = __float_as_uint(s);
                    if (score_bin(bits) >= beta) {
                        pass = true;
                        u32 flat = (u32)row * NCC + (u32)c;
                        key = ((u64)bits << 21) | (u64)(0x1FFFFFu - flat);
                    }
                }
            }
            warp_store(b, pass, key);
        }
    }
}

// one block per batch: filter raw by bin>=beta, bitonic sort desc, keep NPRE
__global__ void __launch_bounds__(1024) k_sort() {
    extern __shared__ u64 sk[];
    __shared__ u32 scount;
    int b = blockIdx.x, tid = threadIdx.x;
    if (tid == 0) scount = 0;
    __syncthreads();
    int beta = g_beta[b];
    u32 cnt = min(g_preCnt[b], (u32)GCAP);
    for (u32 i = tid; i < cnt; i += 1024) {
        u64 key = g_preRaw[(size_t)b * GCAP + i];
        if (score_bin((u32)(key >> 21)) >= beta) {
            u32 p = atomicAdd(&scount, 1u);
            sk[p] = key;
        }
    }
    __syncthreads();
    u32 fc = min(scount, (u32)GCAP);
    u32 P = 2;
    while (P < fc) P <<= 1;
    for (u32 i = fc + tid; i < P; i += 1024) sk[i] = 0ull;
    __syncthreads();
    for (u32 k = 2; k <= P; k <<= 1) {
        for (u32 j = k >> 1; j; j >>= 1) {
            for (u32 i = tid; i < P; i += 1024) {
                u32 l = i ^ j;
                if (l > i) {
                    u64 a = sk[i], c = sk[l];
                    bool desc = ((i & k) == 0);
                    if ((a < c) == desc) { sk[i] = c; sk[l] = a; }
                }
            }
            __syncthreads();
        }
    }
    if (tid == 0) g_preN[b] = min(fc, (u32)NPRE);
    for (int i = tid; i < NPRE; i += 1024)
        g_preSorted[(size_t)b * NPRE + i] = (i < (int)P) ? sk[i] : 0ull;
}

// warp per (class,batch): greedy NMS on sorted prefix, reference-exact FP
__global__ void __launch_bounds__(256) k_nms(const float* __restrict__ pred) {
    __shared__ u16 spos[8][CAPC];
    __shared__ float4 sbox[8][CAPC];
    __shared__ float sarea[8][CAPC];
    __shared__ unsigned char ssup[8][CAPC];
    int b = blockIdx.y, tid = threadIdx.x;
    int w = tid >> 5, lane = tid & 31;
    int myc = blockIdx.x * 8 + w;
    u32 N = g_preN[b];
    const u64* ps = &g_preSorted[(size_t)b * NPRE];
    u32 base = 0;
    for (u32 i = lane; i < ((N + 31) & ~31u); i += 32) {
        bool match = false;
        if (i < N) {
            u32 flat = 0x1FFFFFu - (u32)(ps[i] & 0x1FFFFFu);
            match = (flat % NCC) == (u32)myc;
        }
        u32 m = __ballot_sync(0xffffffffu, match);
        if (match) {
            u32 idx = base + __popc(m & ((1u << lane) - 1u));
            if (idx < CAPC) spos[w][idx] = (u16)i;
        }
        base += __popc(m);
    }
    u32 cnt = min(base, (u32)CAPC);
    float coff = (float)myc * 4096.0f;
    for (u32 j = lane; j < cnt; j += 32) {
        u32 i = spos[w][j];
        u32 flat = 0x1FFFFFu - (u32)(ps[i] & 0x1FFFFFu);
        u32 n = flat / NCC;
        const float* q = pred + ((size_t)b * NN + n) * ROWW;
        float cx = q[0], cy = q[1], ww = q[2], hh = q[3];
        float x1 = __fsub_rn(cx, __fmul_rn(0.5f, ww));
        float y1 = __fsub_rn(cy, __fmul_rn(0.5f, hh));
        float x2 = __fadd_rn(cx, __fmul_rn(0.5f, ww));
        float y2 = __fadd_rn(cy, __fmul_rn(0.5f, hh));
        float ox1 = __fadd_rn(x1, coff), oy1 = __fadd_rn(y1, coff);
        float ox2 = __fadd_rn(x2, coff), oy2 = __fadd_rn(y2, coff);
        sbox[w][j] = make_float4(ox1, oy1, ox2, oy2);
        sarea[w][j] = __fmul_rn(__fsub_rn(ox2, ox1), __fsub_rn(oy2, oy1));
        ssup[w][j] = 0;
    }
    __syncwarp();
    for (u32 m = 0; m < cnt; m++) {
        if (ssup[w][m]) continue;
        if (lane == 0) g_keep[(size_t)b * NPRE + spos[w][m]] = 1;
        float4 bm = sbox[w][m];
        float am = sarea[w][m];
        for (u32 j = m + 1 + lane; j < cnt; j += 32) {
            if (ssup[w][j]) continue;
            float4 bj = sbox[w][j];
            float ltx = fmaxf(bm.x, bj.x), lty = fmaxf(bm.y, bj.y);
            float rbx = fminf(bm.z, bj.z), rby = fminf(bm.w, bj.w);
            float wx = fmaxf(__fsub_rn(rbx, ltx), 0.0f);
            float wy = fmaxf(__fsub_rn(rby, lty), 0.0f);
            float inter = __fmul_rn(wx, wy);
            if (inter > 0.0f) {
                float den = __fadd_rn(__fsub_rn(__fadd_rn(am, sarea[w][j]), inter), 1e-9f);
                if (__fdiv_rn(inter, den) > 0.5f) ssup[w][j] = 1;
            }
        }
        __syncwarp();
    }
}

// block per batch: prefix-scan keep flags, emit first 300 in prefix order
__global__ void __launch_bounds__(256) k_final(const float* __restrict__ pred,
                                               float* __restrict__ out) {
    __shared__ u32 part[256];
    int b = blockIdx.x, tid = threadIdx.x;
    u32 N = g_preN[b];
    float* ob = out + (size_t)b * MAXDET * 6;
    for (int k = tid; k < MAXDET * 6; k += 256) ob[k] = 0.0f;
    u32 s = 0;
    unsigned char f[4];
#pragma unroll
    for (int t = 0; t < 4; t++) {
        u32 i = tid * 4 + t;
        f[t] = (i < N) ? g_keep[(size_t)b * NPRE + i] : 0;
        s += f[t];
    }
    part[tid] = s;
    __syncthreads();
    for (int off = 1; off < 256; off <<= 1) {
        u32 v = (tid >= off) ? part[tid - off] : 0;
        __syncthreads();
        part[tid] += v;
        __syncthreads();
    }
    u32 r = part[tid] - s;
#pragma unroll
    for (int t = 0; t < 4; t++) {
        u32 i = tid * 4 + t;
        if (f[t]) {
            if (r < (u32)MAXDET) {
                u64 key = g_preSorted[(size_t)b * NPRE + i];
                u32 flat = 0x1FFFFFu - (u32)(key & 0x1FFFFFu);
                u32 n = flat / NCC, c = flat - n * NCC;
                const float* q = pred + ((size_t)b * NN + n) * ROWW;
                float cx = q[0], cy = q[1], ww = q[2], hh = q[3];
                float* o = ob + r * 6;
                o[0] = __fsub_rn(cx, __fmul_rn(0.5f, ww));
                o[1] = __fsub_rn(cy, __fmul_rn(0.5f, hh));
                o[2] = __fadd_rn(cx, __fmul_rn(0.5f, ww));
                o[3] = __fadd_rn(cy, __fmul_rn(0.5f, hh));
                o[4] = __uint_as_float((u32)(key >> 21));
                o[5] = (float)c;
            }
            r++;
        }
    }
}

extern "C" void kernel_launch(void* const* d_in, const int* in_sizes, int n_in,
                              void* d_out, int out_size) {
    const float* pred = (const float*)d_in[0];
    float* out = (float*)d_out;
    (void)in_sizes; (void)n_in; (void)out_size;

    cudaFuncSetAttribute(k_sort, cudaFuncAttributeMaxDynamicSharedMemorySize, GCAP * 8);

    k_init<<<64, 256>>>();
    k_pass1<<<dim3(GRID_X, BB), 256>>>(pred);
    k_select<<<BB, 256>>>();
    k_hist_lo<<<dim3(RESCUE_BLKS, BB), 256>>>(pred);     // rescue (grid-stride, ~free)
    k_select2<<<BB, 256>>>();                             // rescue
    k_regather<<<dim3(RESCUE_BLKS, BB), 256>>>(pred);     // rescue (grid-stride, ~free)
    k_sort<<<BB, 1024, GCAP * 8>>>();
    k_nms<<<dim3(NCC / 8, BB), 256>>>(pred);
    k_final<<<BB, 256>>>(pred, out);
}

// round 8
// speedup vs baseline: 1.0500x; 1.0419x over previous
#include <cuda_runtime.h>
#include <cstdint>

#define BB 16
#define NN 25200
#define NCC 80
#define ROWW 85
#define MAXDET 300
#define NPRE 1024
#define GCAP 8192
#define NBINS 1536
#define BASE_BITS 0x3EC00000u
#define HSHIFT 13
#define RPB 256
#define GRID_X ((NN + RPB - 1) / RPB)
#define CAPC 128

typedef unsigned long long u64;
typedef unsigned int u32;
typedef unsigned short u16;

// ---------------- scratch ----------------
static __device__ u32 g_hist[BB * NBINS];
static __device__ int g_beta[BB];
static __device__ u32 g_flag[BB];
static __device__ u32 g_preCnt[BB];
static __device__ u64 g_preRaw[BB * GCAP];
static __device__ u64 g_preSorted[BB * NPRE];
static __device__ u32 g_preN[BB];
static __device__ unsigned char g_keep[BB * NPRE];

__device__ __forceinline__ int score_bin(u32 bits) {
    int bin = (int)((bits - BASE_BITS) >> HSHIFT);
    return bin > (NBINS - 1) ? (NBINS - 1) : bin;
}
#define PB90 (score_bin(0x3F666666u))   /* bin of 0.90f */
#define PB96 (score_bin(0x3F75C28Fu))   /* bin of 0.96f */

__device__ __forceinline__ void warp_store(int b, bool pass, u64 key) {
    u32 m = __ballot_sync(0xffffffffu, pass);
    if (!m) return;
    int lane = threadIdx.x & 31;
    int leader = __ffs(m) - 1;
    u32 base = 0;
    if (lane == leader) base = atomicAdd(&g_preCnt[b], (u32)__popc(m));
    base = __shfl_sync(0xffffffffu, base, leader);
    if (pass) {
        u32 slot = base + __popc(m & ((1u << lane) - 1u));
        if (slot < GCAP) g_preRaw[(size_t)b * GCAP + slot] = key;
    }
}

// ---------------- kernels ----------------
__global__ void k_init() {
    int i = blockIdx.x * blockDim.x + threadIdx.x;
    int st = gridDim.x * blockDim.x;
    for (int k = i; k < BB * NBINS; k += st) g_hist[k] = 0;
    for (int k = i; k < BB * NPRE / 4; k += st) ((u32*)g_keep)[k] = 0;
    if (i < BB) { g_preCnt[i] = 0; g_flag[i] = 0; }
}

// single streaming pass: obj prefilter (1 sector/row), compact passing rows,
// then warps read cls scores only for passing rows.
// histogram scores > 0.9; store candidates with bin > PB96.
__global__ void __launch_bounds__(256) k_pass1(const float* __restrict__ pred) {
    __shared__ u32 sh[NBINS];
    __shared__ float sobj[RPB];
    __shared__ u16 srow[RPB];
    __shared__ u32 srn;
    int b = blockIdx.y, tid = threadIdx.x;
    int row0 = blockIdx.x * RPB;
    for (int i = tid; i < NBINS; i += 256) sh[i] = 0;
    if (tid == 0) srn = 0;
    __syncthreads();
    int row = row0 + tid;
    if (row < NN) {
        float obj = pred[((size_t)b * NN + row) * ROWW + 4];
        if (obj > 0.4f) {
            u32 p = atomicAdd(&srn, 1u);
            srow[p] = (u16)tid;
            sobj[p] = obj;
        }
    }
    __syncthreads();
    int nr = (int)srn;
    int warp = tid >> 5, lane = tid & 31;
    for (int i = warp; i < nr; i += 8) {
        int rowg = row0 + srow[i];
        const float* q = pred + ((size_t)b * NN + rowg) * ROWW;
        float obj = sobj[i];
#pragma unroll
        for (int k = 0; k < 3; k++) {
            int c = k * 32 + lane;
            bool pass = false;
            u64 key = 0;
            if (c < NCC) {
                float s = __fmul_rn(q[5 + c], obj);
                if (s > 0.9f) {
                    u32 bits = __float_as_uint(s);
                    int bin = score_bin(bits);
                    atomicAdd(&sh[bin], 1u);
                    if (bin > PB96) {
                        pass = true;
                        u32 flat = (u32)rowg * NCC + (u32)c;
                        key = ((u64)bits << 21) | (u64)(0x1FFFFFu - flat);
                    }
                }
            }
            warp_store(b, pass, key);
        }
    }
    __syncthreads();
    for (int i = tid; i < NBINS; i += 256)
        if (sh[i]) atomicAdd(&g_hist[b * NBINS + i], sh[i]);
}

// exact top-NPRE boundary bin from the (partial, >PB90-complete) histogram
__global__ void k_select() {
    __shared__ u32 h[NBINS];
    __shared__ u32 part[256];
    int b = blockIdx.x, tid = threadIdx.x;
    for (int i = tid; i < NBINS; i += 256)
        h[i] = (i > PB90) ? g_hist[b * NBINS + i] : 0u;
    __syncthreads();
    u32 ps = 0;
    for (int k = 0; k < 6; k++) ps += h[tid * 6 + k];
    part[tid] = ps;
    __syncthreads();
    if (tid == 0) {
        u32 cum = 0; int beta = -1;
        for (int t = 255; t >= 0; --t) {
            if (cum + part[t] >= (u32)NPRE) {
                for (int bin = t * 6 + 5; bin >= t * 6; --bin) {
                    u32 c = h[bin];
                    if (cum + c >= (u32)NPRE) { beta = bin; break; }
                    cum += c;
                }
                break;
            }
            cum += part[t];
        }
        if (beta < 0 || beta <= PB96) g_flag[b] = 1;   // rescue
        else g_beta[b] = beta;
    }
}

// single merged rescue kernel: one block per batch; early exit when flag==0.
// Completes the (0.4, 0.9] histogram, computes exact beta, regathers.
__global__ void __launch_bounds__(256) k_rescue(const float* __restrict__ pred) {
    int b = blockIdx.x;
    if (!g_flag[b]) return;
    __shared__ u32 sh[NBINS];
    int tid = threadIdx.x;
    int warp = tid >> 5, lane = tid & 31;
    for (int i = tid; i < NBINS; i += 256) sh[i] = 0;
    __syncthreads();
    // complete the histogram for scores in (0.4, 0.9]
    for (int row = warp; row < NN; row += 8) {
        const float* q = pred + ((size_t)b * NN + row) * ROWW;
        float obj = q[4];
        if (obj > 0.4f) {
#pragma unroll
            for (int k = 0; k < 3; k++) {
                int c = k * 32 + lane;
                if (c < NCC) {
                    float s = __fmul_rn(q[5 + c], obj);
                    if (s > 0.4f && !(s > 0.9f))
                        atomicAdd(&sh[score_bin(__float_as_uint(s))], 1u);
                }
            }
        }
    }
    __syncthreads();
    for (int i = tid; i < NBINS; i += 256) sh[i] += g_hist[b * NBINS + i];
    __syncthreads();
    if (tid == 0) {
        u32 cum = 0; int beta = 0;
        for (int bin = NBINS - 1; bin >= 0; --bin) {
            u32 c = sh[bin];
            if (cum + c >= (u32)NPRE) { beta = bin; break; }
            cum += c;
        }
        g_beta[b] = beta;
        g_preCnt[b] = 0;
    }
    __syncthreads();
    int beta = g_beta[b];
    // exact regather of all candidates with bin >= beta
    for (int row = warp; row < NN; row += 8) {
        const float* q = pred + ((size_t)b * NN + row) * ROWW;
        float obj = q[4];
        bool rowok = (obj > 0.4f);
#pragma unroll
        for (int k = 0; k < 3; k++) {
            int c = k * 32 + lane;
            bool pass = false;
            u64 key = 0;
            if (rowok && c < NCC) {
                float s = __fmul_rn(q[5 + c], obj);
                if (s > 0.4f) {
                    u32 bits = __float_as_uint(s);
                    if (score_bin(bits) >= beta) {
                        pass = true;
                        u32 flat = (u32)row * NCC + (u32)c;
                        key = ((u64)bits << 21) | (u64)(0x1FFFFFu - flat);
                    }
                }
            }
            warp_store(b, pass, key);
        }
    }
}

// one block per batch: filter raw by bin>=beta, bitonic sort desc, keep NPRE
__global__ void __launch_bounds__(1024) k_sort() {
    extern __shared__ u64 sk[];
    __shared__ u32 scount;
    int b = blockIdx.x, tid = threadIdx.x;
    if (tid == 0) scount = 0;
    __syncthreads();
    int beta = g_beta[b];
    u32 cnt = min(g_preCnt[b], (u32)GCAP);
    for (u32 i = tid; i < cnt; i += 1024) {
        u64 key = g_preRaw[(size_t)b * GCAP + i];
        if (score_bin((u32)(key >> 21)) >= beta) {
            u32 p = atomicAdd(&scount, 1u);
            sk[p] = key;
        }
    }
    __syncthreads();
    u32 fc = min(scount, (u32)GCAP);
    u32 P = 2;
    while (P < fc) P <<= 1;
    for (u32 i = fc + tid; i < P; i += 1024) sk[i] = 0ull;
    __syncthreads();
    for (u32 k = 2; k <= P; k <<= 1) {
        for (u32 j = k >> 1; j; j >>= 1) {
            for (u32 i = tid; i < P; i += 1024) {
                u32 l = i ^ j;
                if (l > i) {
                    u64 a = sk[i], c = sk[l];
                    bool desc = ((i & k) == 0);
                    if ((a < c) == desc) { sk[i] = c; sk[l] = a; }
                }
            }
            __syncthreads();
        }
    }
    if (tid == 0) g_preN[b] = min(fc, (u32)NPRE);
    for (int i = tid; i < NPRE; i += 1024)
        g_preSorted[(size_t)b * NPRE + i] = (i < (int)P) ? sk[i] : 0ull;
}

// warp per (class,batch): greedy NMS on sorted prefix, reference-exact FP
__global__ void __launch_bounds__(256) k_nms(const float* __restrict__ pred) {
    __shared__ u16 spos[8][CAPC];
    __shared__ float4 sbox[8][CAPC];
    __shared__ float sarea[8][CAPC];
    __shared__ unsigned char ssup[8][CAPC];
    int b = blockIdx.y, tid = threadIdx.x;
    int w = tid >> 5, lane = tid & 31;
    int myc = blockIdx.x * 8 + w;
    u32 N = g_preN[b];
    const u64* ps = &g_preSorted[(size_t)b * NPRE];
    u32 base = 0;
    for (u32 i = lane; i < ((N + 31) & ~31u); i += 32) {
        bool match = false;
        if (i < N) {
            u32 flat = 0x1FFFFFu - (u32)(ps[i] & 0x1FFFFFu);
            match = (flat % NCC) == (u32)myc;
        }
        u32 m = __ballot_sync(0xffffffffu, match);
        if (match) {
            u32 idx = base + __popc(m & ((1u << lane) - 1u));
            if (idx < CAPC) spos[w][idx] = (u16)i;
        }
        base += __popc(m);
    }
    u32 cnt = min(base, (u32)CAPC);
    float coff = (float)myc * 4096.0f;
    for (u32 j = lane; j < cnt; j += 32) {
        u32 i = spos[w][j];
        u32 flat = 0x1FFFFFu - (u32)(ps[i] & 0x1FFFFFu);
        u32 n = flat / NCC;
        const float* q = pred + ((size_t)b * NN + n) * ROWW;
        float cx = q[0], cy = q[1], ww = q[2], hh = q[3];
        float x1 = __fsub_rn(cx, __fmul_rn(0.5f, ww));
        float y1 = __fsub_rn(cy, __fmul_rn(0.5f, hh));
        float x2 = __fadd_rn(cx, __fmul_rn(0.5f, ww));
        float y2 = __fadd_rn(cy, __fmul_rn(0.5f, hh));
        float ox1 = __fadd_rn(x1, coff), oy1 = __fadd_rn(y1, coff);
        float ox2 = __fadd_rn(x2, coff), oy2 = __fadd_rn(y2, coff);
        sbox[w][j] = make_float4(ox1, oy1, ox2, oy2);
        sarea[w][j] = __fmul_rn(__fsub_rn(ox2, ox1), __fsub_rn(oy2, oy1));
        ssup[w][j] = 0;
    }
    __syncwarp();
    for (u32 m = 0; m < cnt; m++) {
        if (ssup[w][m]) continue;
        if (lane == 0) g_keep[(size_t)b * NPRE + spos[w][m]] = 1;
        float4 bm = sbox[w][m];
        float am = sarea[w][m];
        for (u32 j = m + 1 + lane; j < cnt; j += 32) {
            if (ssup[w][j]) continue;
            float4 bj = sbox[w][j];
            float ltx = fmaxf(bm.x, bj.x), lty = fmaxf(bm.y, bj.y);
            float rbx = fminf(bm.z, bj.z), rby = fminf(bm.w, bj.w);
            float wx = fmaxf(__fsub_rn(rbx, ltx), 0.0f);
            float wy = fmaxf(__fsub_rn(rby, lty), 0.0f);
            float inter = __fmul_rn(wx, wy);
            if (inter > 0.0f) {
                float den = __fadd_rn(__fsub_rn(__fadd_rn(am, sarea[w][j]), inter), 1e-9f);
                if (__fdiv_rn(inter, den) > 0.5f) ssup[w][j] = 1;
            }
        }
        __syncwarp();
    }
}

// block per batch: prefix-scan keep flags, emit first 300 in prefix order
__global__ void __launch_bounds__(256) k_final(const float* __restrict__ pred,
                                               float* __restrict__ out) {
    __shared__ u32 part[256];
    int b = blockIdx.x, tid = threadIdx.x;
    u32 N = g_preN[b];
    float* ob = out + (size_t)b * MAXDET * 6;
    for (int k = tid; k < MAXDET * 6; k += 256) ob[k] = 0.0f;
    u32 s = 0;
    unsigned char f[4];
#pragma unroll
    for (int t = 0; t < 4; t++) {
        u32 i = tid * 4 + t;
        f[t] = (i < N) ? g_keep[(size_t)b * NPRE + i] : 0;
        s += f[t];
    }
    part[tid] = s;
    __syncthreads();
    for (int off = 1; off < 256; off <<= 1) {
        u32 v = (tid >= off) ? part[tid - off] : 0;
        __syncthreads();
        part[tid] += v;
        __syncthreads();
    }
    u32 r = part[tid] - s;
#pragma unroll
    for (int t = 0; t < 4; t++) {
        u32 i = tid * 4 + t;
        if (f[t]) {
            if (r < (u32)MAXDET) {
                u64 key = g_preSorted[(size_t)b * NPRE + i];
                u32 flat = 0x1FFFFFu - (u32)(key & 0x1FFFFFu);
                u32 n = flat / NCC, c = flat - n * NCC;
                const float* q = pred + ((size_t)b * NN + n) * ROWW;
                float cx = q[0], cy = q[1], ww = q[2], hh = q[3];
                float* o = ob + r * 6;
                o[0] = __fsub_rn(cx, __fmul_rn(0.5f, ww));
                o[1] = __fsub_rn(cy, __fmul_rn(0.5f, hh));
                o[2] = __fadd_rn(cx, __fmul_rn(0.5f, ww));
                o[3] = __fadd_rn(cy, __fmul_rn(0.5f, hh));
                o[4] = __uint_as_float((u32)(key >> 21));
                o[5] = (float)c;
            }
            r++;
        }
    }
}

extern "C" void kernel_launch(void* const* d_in, const int* in_sizes, int n_in,
                              void* d_out, int out_size) {
    const float* pred = (const float*)d_in[0];
    float* out = (float*)d_out;
    (void)in_sizes; (void)n_in; (void)out_size;

    cudaFuncSetAttribute(k_sort, cudaFuncAttributeMaxDynamicSharedMemorySize, GCAP * 8);

    k_init<<<64, 256>>>();
    k_pass1<<<dim3(GRID_X, BB), 256>>>(pred);
    k_select<<<BB, 256>>>();
    k_rescue<<<BB, 256>>>(pred);        // merged rescue (early-exit, ~free)
    k_sort<<<BB, 1024, GCAP * 8>>>();
    k_nms<<<dim3(NCC / 8, BB), 256>>>(pred);
    k_final<<<BB, 256>>>(pred, out);
}